// round 8
// baseline (speedup 1.0000x reference)
#include <cuda_runtime.h>
#include <cuda_bf16.h>
#include <cstdint>

#define B_SZ 2048
#define H_SZ 512
#define D_SZ 32

// ---------------- scratch (device globals; no allocation allowed) ----------
__device__ __align__(16) __nv_bfloat16 g_H1h[B_SZ * H_SZ];
__device__ __align__(16) __nv_bfloat16 g_H1l[B_SZ * H_SZ];
__device__ __align__(16) float         g_D1 [B_SZ * H_SZ];   // 1 - h1^2
__device__ __align__(16) float         g_H2 [B_SZ * H_SZ];
__device__ __align__(16) __nv_bfloat16 g_D2h[B_SZ * H_SZ];   // 1 - h2^2 split
__device__ __align__(16) __nv_bfloat16 g_D2l[B_SZ * H_SZ];
__device__ __align__(16) __nv_bfloat16 g_Bt0h[H_SZ * H_SZ];  // W2^T split
__device__ __align__(16) __nv_bfloat16 g_Bt0l[H_SZ * H_SZ];
__device__ __align__(16) __nv_bfloat16 g_Bdvh[H_SZ * H_SZ];  // E[n][k] split
__device__ __align__(16) __nv_bfloat16 g_Bdvl[H_SZ * H_SZ];
__device__ float g_divpart[8 * B_SZ];

// ---------------- helpers ---------------------------------------------------
__device__ __forceinline__ void bf16split(float x, __nv_bfloat16& h, __nv_bfloat16& l) {
    h = __float2bfloat16_rn(x);
    l = __float2bfloat16_rn(x - __bfloat162float(h));
}
__device__ __forceinline__ uint32_t smem_u32(const void* p) {
    return (uint32_t)__cvta_generic_to_shared(p);
}
__device__ __forceinline__ void cp16(uint32_t dst, const void* src) {
    asm volatile("cp.async.cg.shared.global [%0], [%1], 16;" :: "r"(dst), "l"(src));
}
#define CP_COMMIT() asm volatile("cp.async.commit_group;" ::: "memory")
#define CP_WAIT(n)  asm volatile("cp.async.wait_group %0;" :: "n"(n) : "memory")

#define LDSM4(d, addr)                                                          \
    asm volatile("ldmatrix.sync.aligned.m8n8.x4.shared.b16 {%0,%1,%2,%3}, [%4];"\
        : "=r"((d)[0]), "=r"((d)[1]), "=r"((d)[2]), "=r"((d)[3]) : "r"(addr))

#define MMA_BF16(c, a, b0v, b1v)                                                \
    asm volatile("mma.sync.aligned.m16n8k16.row.col.f32.bf16.bf16.f32 "         \
        "{%0,%1,%2,%3},{%4,%5,%6,%7},{%8,%9},{%0,%1,%2,%3};"                    \
        : "+f"((c)[0]), "+f"((c)[1]), "+f"((c)[2]), "+f"((c)[3])                 \
        : "r"((a)[0]), "r"((a)[1]), "r"((a)[2]), "r"((a)[3]), "r"(b0v), "r"(b1v))

// ---------------------------------------------------------------------------
// K0: g_Bt0*[n][k] = split(W2[k][n]);
//     g_Bdv*[n][k] = split(W2[n][k] * sum_j W1[j][n]*W3[k][j])
// ---------------------------------------------------------------------------
__global__ void k0_pre(const float* __restrict__ W1,
                       const float* __restrict__ W2,
                       const float* __restrict__ W3) {
    __shared__ float tW2[32][33];
    __shared__ float sW3[32][33];
    const int tx = threadIdx.x, ty = threadIdx.y;
    const int k0 = blockIdx.x * 32, n0 = blockIdx.y * 32;

    tW2[ty][tx] = W2[(k0 + ty) * H_SZ + n0 + tx];
    sW3[ty][tx] = W3[(k0 + ty) * D_SZ + tx];
    __syncthreads();

    const int n = n0 + ty;
    const int k = k0 + tx;
    bf16split(tW2[tx][ty], g_Bt0h[n * H_SZ + k], g_Bt0l[n * H_SZ + k]);

    float s = 0.f;
#pragma unroll
    for (int j = 0; j < D_SZ; j++)
        s = fmaf(W1[j * H_SZ + n], sW3[tx][j], s);
    bf16split(W2[n * H_SZ + k] * s, g_Bdvh[n * H_SZ + k], g_Bdvl[n * H_SZ + k]);
}

// ---------------------------------------------------------------------------
// K1: H1 = tanh([x,t] @ W1 + b1) -> bf16 split; D1 = 1 - H1^2 (fp32)
// ---------------------------------------------------------------------------
__global__ void __launch_bounds__(512) k1_h1(const float* __restrict__ t,
                                             const float* __restrict__ x,
                                             const float* __restrict__ W1,
                                             const float* __restrict__ b1) {
    __shared__ float sx[16][33];
    const int b0 = blockIdx.x * 16;
    const int m  = threadIdx.x;
    for (int idx = m; idx < 16 * 33; idx += 512) {
        int r = idx / 33, j = idx % 33;
        sx[r][j] = (j == 32) ? t[0] : x[(b0 + r) * 33 + j];
    }
    float w[33];
#pragma unroll
    for (int j = 0; j < 33; j++) w[j] = W1[j * H_SZ + m];
    float bb = b1[m];
    __syncthreads();
#pragma unroll 4
    for (int r = 0; r < 16; r++) {
        float acc = bb;
#pragma unroll
        for (int j = 0; j < 33; j++) acc = fmaf(sx[r][j], w[j], acc);
        float h = tanhf(acc);
        const int o = (b0 + r) * H_SZ + m;
        bf16split(h, g_H1h[o], g_H1l[o]);
        g_D1[o] = 1.f - h * h;
    }
}

// ---------------------------------------------------------------------------
// bf16-split mma.sync GEMM, cp.async 4-stage pipeline, 512 threads.
// CTA tile 128(M) x 64(N), K=512 in 16 chunks of 32. grid (16,8).
// 16 warps: 4m x 4n, warp tile 32x16.
// MODE 0: C = H1 @ W2   -> H2 = tanh(C + b2), D2 = 1-H2^2 (split)
// MODE 1: C = D2 @ E^T  -> divpart[ny][row] = sum_col D1[row,col]*C[row,col]
// ---------------------------------------------------------------------------
#define SA_H 0
#define SA_L 10240
#define SB_H 20480
#define SB_L 25600
#define STG  30720
#define NSTAGE 4
#define GEMM_SMEM (STG * NSTAGE)   // 122880

template <int MODE>
__global__ void __launch_bounds__(512) gemm_mma(const float* __restrict__ bias) {
    extern __shared__ __align__(16) unsigned char smem[];
    const int tid  = threadIdx.x;
    const int lane = tid & 31;
    const int wid  = tid >> 5;
    const int wm   = wid & 3;        // 0..3, 32 M-rows each
    const int wn   = wid >> 2;       // 0..3, 16 N-cols each
    const int bm   = blockIdx.x * 128;
    const int bn   = blockIdx.y * 64;

    const __nv_bfloat16* __restrict__ Ah = (MODE == 0) ? g_H1h : g_D2h;
    const __nv_bfloat16* __restrict__ Al = (MODE == 0) ? g_H1l : g_D2l;
    const __nv_bfloat16* __restrict__ Bh = (MODE == 0) ? g_Bt0h : g_Bdvh;
    const __nv_bfloat16* __restrict__ Bl = (MODE == 0) ? g_Bt0l : g_Bdvl;

    const uint32_t sb = smem_u32(smem);

    // copy assignment: 3 cp.async(16B) per thread per chunk
    const int arow = tid >> 2;                  // 0..127
    const int aq16 = (tid & 3) * 16;            // byte quad in row
    const size_t aoff = (size_t)(bm + arow) * H_SZ + (tid & 3) * 8;
    const uint32_t dRA = arow * 80 + aq16;

    const int bsel = tid >> 8;                  // 0: Bh, 1: Bl
    const int brow = (tid >> 2) & 63;
    const size_t boff = (size_t)(bn + brow) * H_SZ + (tid & 3) * 8;
    const uint32_t dRB = (bsel ? SB_L : SB_H) + brow * 80 + (tid & 3) * 16;
    const __nv_bfloat16* __restrict__ Bsrc = bsel ? Bl : Bh;

    float cacc[2][2][4] = {};

    // ldmatrix lane addressing within warp
    const int lrow = (lane & 7) + ((lane >> 3) & 1) * 8;
    const int lcol = ((lane >> 4) & 1) * 16;

#define ISSUE(c) do {                                                           \
        const int _k0 = (c) * 32;                                               \
        const uint32_t _st = sb + ((c) & (NSTAGE - 1)) * STG;                   \
        cp16(_st + SA_H + dRA, Ah + aoff + _k0);                                \
        cp16(_st + SA_L + dRA, Al + aoff + _k0);                                \
        cp16(_st + dRB,        Bsrc + boff + _k0);                              \
    } while (0)

    ISSUE(0); CP_COMMIT();
    ISSUE(1); CP_COMMIT();
    ISSUE(2); CP_COMMIT();

#pragma unroll 1
    for (int c = 0; c < 16; ++c) {
        CP_WAIT(2);
        __syncthreads();                 // stage c ready; stage c-1 fully consumed
        if (c + 3 < 16) ISSUE(c + 3);
        CP_COMMIT();

        const uint32_t st = sb + (c & (NSTAGE - 1)) * STG;
#pragma unroll
        for (int kk = 0; kk < 2; kk++) {
            uint32_t afh[2][4], afl[2][4], bfh[4], bfl[4];
#pragma unroll
            for (int m = 0; m < 2; m++) {
                uint32_t ad = st + SA_H +
                    (uint32_t)((wm * 32 + m * 16 + lrow) * 80 + lcol + kk * 32);
                LDSM4(afh[m], ad);
                LDSM4(afl[m], ad + (SA_L - SA_H));
            }
            {
                uint32_t bd = st + SB_H +
                    (uint32_t)((wn * 16 + lrow) * 80 + lcol + kk * 32);
                LDSM4(bfh, bd);
                LDSM4(bfl, bd + (SB_L - SB_H));
            }
            // pass-major ordering: chained MMAs on one accumulator are 4 apart
#pragma unroll
            for (int m = 0; m < 2; m++)
#pragma unroll
                for (int n = 0; n < 2; n++)
                    MMA_BF16(cacc[m][n], afh[m], bfh[n], bfh[n + 2]);
#pragma unroll
            for (int m = 0; m < 2; m++)
#pragma unroll
                for (int n = 0; n < 2; n++)
                    MMA_BF16(cacc[m][n], afh[m], bfl[n], bfl[n + 2]);
#pragma unroll
            for (int m = 0; m < 2; m++)
#pragma unroll
                for (int n = 0; n < 2; n++)
                    MMA_BF16(cacc[m][n], afl[m], bfh[n], bfh[n + 2]);
        }
    }
#undef ISSUE

    __syncthreads();

    if (MODE == 0) {
#pragma unroll
        for (int m = 0; m < 2; m++)
#pragma unroll
            for (int h = 0; h < 2; h++) {
                const int row = bm + wm * 32 + m * 16 + (lane >> 2) + h * 8;
#pragma unroll
                for (int n = 0; n < 2; n++) {
                    const int col = bn + wn * 16 + n * 8 + ((lane & 3) << 1);
                    float v0 = tanhf(cacc[m][n][h * 2 + 0] + __ldg(&bias[col + 0]));
                    float v1 = tanhf(cacc[m][n][h * 2 + 1] + __ldg(&bias[col + 1]));
                    *(float2*)&g_H2[(size_t)row * H_SZ + col] = make_float2(v0, v1);
                    float d0 = 1.f - v0 * v0, d1v = 1.f - v1 * v1;
                    __nv_bfloat16 h0, l0, h1b, l1;
                    bf16split(d0, h0, l0);
                    bf16split(d1v, h1b, l1);
                    *(__nv_bfloat162*)&g_D2h[(size_t)row * H_SZ + col] =
                        __nv_bfloat162(h0, h1b);
                    *(__nv_bfloat162*)&g_D2l[(size_t)row * H_SZ + col] =
                        __nv_bfloat162(l0, l1);
                }
            }
    } else {
        float sr[4] = {0.f, 0.f, 0.f, 0.f};
#pragma unroll
        for (int m = 0; m < 2; m++)
#pragma unroll
            for (int h = 0; h < 2; h++) {
                const int row = bm + wm * 32 + m * 16 + (lane >> 2) + h * 8;
#pragma unroll
                for (int n = 0; n < 2; n++) {
                    const int col = bn + wn * 16 + n * 8 + ((lane & 3) << 1);
                    float2 w = *(const float2*)&g_D1[(size_t)row * H_SZ + col];
                    sr[m * 2 + h] += w.x * cacc[m][n][h * 2 + 0]
                                   + w.y * cacc[m][n][h * 2 + 1];
                }
            }
#pragma unroll
        for (int i = 0; i < 4; i++) {
            sr[i] += __shfl_xor_sync(0xffffffffu, sr[i], 1);
            sr[i] += __shfl_xor_sync(0xffffffffu, sr[i], 2);
        }
        float* red = (float*)smem;   // reuse tile smem: 128 rows x 4 wn
        if ((lane & 3) == 0) {
#pragma unroll
            for (int m = 0; m < 2; m++)
#pragma unroll
                for (int h = 0; h < 2; h++) {
                    const int rl = wm * 32 + m * 16 + (lane >> 2) + h * 8;
                    red[rl * 4 + wn] = sr[m * 2 + h];
                }
        }
        __syncthreads();
        if (tid < 128)
            g_divpart[blockIdx.y * B_SZ + bm + tid] =
                (red[tid * 4] + red[tid * 4 + 1]) +
                (red[tid * 4 + 2] + red[tid * 4 + 3]);
    }
}

// ---------------------------------------------------------------------------
// K4: dx[b][d] = b3[d] + sum_k H2[b,k]*W3[k,d]; div[b] = sum of 8 partials.
// 512 threads, 16 rows/CTA, 2-way split accumulator chains.
// ---------------------------------------------------------------------------
__global__ void __launch_bounds__(512) k4_out(const float* __restrict__ W3,
                                              const float* __restrict__ b3,
                                              float* __restrict__ out) {
    __shared__ float sh[16 * 512];
    const int b0  = blockIdx.x * 16;
    const int tid = threadIdx.x;
    for (int idx = tid; idx < 16 * 512; idx += 512)
        sh[idx] = g_H2[b0 * 512 + idx];
    __syncthreads();
    const int r = tid >> 5;
    const int d = tid & 31;
    const int b = b0 + r;
    float acc0 = 0.f, acc1 = 0.f;
#pragma unroll 8
    for (int k = 0; k < 256; k++) {
        acc0 = fmaf(sh[r * 512 + k],       W3[k * D_SZ + d],         acc0);
        acc1 = fmaf(sh[r * 512 + 256 + k], W3[(256 + k) * D_SZ + d], acc1);
    }
    out[b * 33 + d] = b3[d] + acc0 + acc1;
    if (d == 0) {
        float s = 0.f;
#pragma unroll
        for (int p = 0; p < 8; p++) s += g_divpart[p * B_SZ + b];
        out[b * 33 + 32] = s;
    }
}

// ---------------------------------------------------------------------------
extern "C" void kernel_launch(void* const* d_in, const int* in_sizes, int n_in,
                              void* d_out, int out_size) {
    const float* t  = (const float*)d_in[0];
    const float* x  = (const float*)d_in[1];
    const float* W1 = (const float*)d_in[2];
    const float* b1 = (const float*)d_in[3];
    const float* W2 = (const float*)d_in[4];
    const float* b2 = (const float*)d_in[5];
    const float* W3 = (const float*)d_in[6];
    const float* b3 = (const float*)d_in[7];
    float* out = (float*)d_out;

    cudaFuncSetAttribute(gemm_mma<0>, cudaFuncAttributeMaxDynamicSharedMemorySize, GEMM_SMEM);
    cudaFuncSetAttribute(gemm_mma<1>, cudaFuncAttributeMaxDynamicSharedMemorySize, GEMM_SMEM);

    k0_pre<<<dim3(16, 16), dim3(32, 32)>>>(W1, W2, W3);
    k1_h1<<<128, 512>>>(t, x, W1, b1);
    dim3 g(16, 8);
    gemm_mma<0><<<g, 512, GEMM_SMEM>>>(b2);        // H2 = tanh(H1 @ W2 + b2), D2 split
    gemm_mma<1><<<g, 512, GEMM_SMEM>>>(nullptr);   // divergence partials
    k4_out<<<B_SZ / 16, 512>>>(W3, b3, out);
}